// round 15
// baseline (speedup 1.0000x reference)
#include <cuda_runtime.h>
#include <cuda_bf16.h>
#include <math.h>
#include <stdint.h>

#define HEADS 8
#define BATCH 4
#define CDIM 256
#define DK 32
#define DQK 64
#define DD 12
#define NTOK 1728
#define BH 32
#define JTILES 27
#define QTILES 14
#define EXP_SHIFT 10.0f

// ---------------- global scratch ----------------
__device__ __nv_bfloat16 gQhi[BH * NTOK * DQK];
__device__ __nv_bfloat16 gQlo[BH * NTOK * DQK];
__device__ __nv_bfloat16 gKhi[BH * NTOK * DQK];
__device__ __nv_bfloat16 gKlo[BH * NTOK * DQK];
__device__ __nv_bfloat16 gVhi[BH * DK * NTOK];
__device__ __nv_bfloat16 gVlo[BH * DK * NTOK];
__device__ __nv_bfloat16 gWhi[3 * CDIM * CDIM];
__device__ __nv_bfloat16 gWlo[3 * CDIM * CDIM];
__device__ __nv_bfloat16 gXThi[BATCH * NTOK * CDIM];
__device__ __nv_bfloat16 gXTlo[BATCH * NTOK * CDIM];
// split-K attention partials (additive thanks to no-max shifted softmax)
__device__ float gOp0[BH * DK * NTOK];
__device__ float gOp1[BH * DK * NTOK];
__device__ float gLp0[BH * NTOK];
__device__ float gLp1[BH * NTOK];
__device__ int   gCnt[QTILES * BH];

// ---------------- helpers ----------------
__device__ __forceinline__ uint32_t smem_u32(const void* p) {
    uint32_t a;
    asm("{ .reg .u64 t; cvta.to.shared.u64 t, %1; cvt.u32.u64 %0, t; }"
        : "=r"(a) : "l"(p));
    return a;
}
__device__ __forceinline__ void ldsm4(uint32_t addr, uint32_t r[4]) {
    asm volatile("ldmatrix.sync.aligned.m8n8.x4.shared.b16 {%0,%1,%2,%3}, [%4];"
        : "=r"(r[0]), "=r"(r[1]), "=r"(r[2]), "=r"(r[3]) : "r"(addr));
}
__device__ __forceinline__ void mma16816(float c[4], const uint32_t a[4],
                                         uint32_t b0, uint32_t b1) {
    asm volatile(
        "mma.sync.aligned.m16n8k16.row.col.f32.bf16.bf16.f32 "
        "{%0,%1,%2,%3}, {%4,%5,%6,%7}, {%8,%9}, {%0,%1,%2,%3};"
        : "+f"(c[0]), "+f"(c[1]), "+f"(c[2]), "+f"(c[3])
        : "r"(a[0]), "r"(a[1]), "r"(a[2]), "r"(a[3]), "r"(b0), "r"(b1));
}
__device__ __forceinline__ uint32_t cvt_bf16x2(float lo, float hi) {
    uint32_t d;
    asm("cvt.rn.bf16x2.f32 %0, %1, %2;" : "=r"(d) : "f"(hi), "f"(lo));
    return d;
}
__device__ __forceinline__ float bflo_f(uint32_t p) { return __uint_as_float(p << 16); }
__device__ __forceinline__ float bfhi_f(uint32_t p) { return __uint_as_float(p & 0xffff0000u); }
__device__ __forceinline__ void split_pack2(float v0, float v1,
                                            uint32_t& hi, uint32_t& lo) {
    hi = cvt_bf16x2(v0, v1);
    lo = cvt_bf16x2(v0 - bflo_f(hi), v1 - bfhi_f(hi));
}
__device__ __forceinline__ void cp16(uint32_t dst, const void* src) {
    asm volatile("cp.async.cg.shared.global [%0], [%1], 16;"
                 :: "r"(dst), "l"(src) : "memory");
}

// ---------------------------------------------------------------------------
// Kernel 1 (merged prep): pos | wsplit | xsplit + counter reset.
// ---------------------------------------------------------------------------
__global__ __launch_bounds__(256) void prep_kernel(
    const float* __restrict__ x,
    const float* __restrict__ wq, const float* __restrict__ wk,
    const float* __restrict__ wv,
    const float* __restrict__ rel_d, const float* __restrict__ rel_h,
    const float* __restrict__ rel_w) {
    __shared__ float Xs[64][68];
    int bid = blockIdx.x;
    int tid = threadIdx.x;

    if (bid < 2 && bid * 256 + tid < QTILES * BH)
        gCnt[bid * 256 + tid] = 0;

    if (bid < 216) {
        // ---- pos ----
        int idx = bid * 256 + tid;
        int n = idx % NTOK;
        int bh = idx / NTOK;
        int b = bh >> 3, h = bh & 7;
        int hi_ = n % DD;
        int wi = (n / DD) % DD;
        int di = n / (DD * DD);
        uint32_t ph[16], pl[16];
#pragma unroll
        for (int j = 0; j < 16; j++) {
            int dd0 = 2 * j, dd1 = 2 * j + 1;
            float v0 = rel_d[(h * DK + dd0) * DD + di] +
                       rel_h[(h * DK + dd0) * DD + hi_] +
                       rel_w[(h * DK + dd0) * DD + wi];
            float v1 = rel_d[(h * DK + dd1) * DD + di] +
                       rel_h[(h * DK + dd1) * DD + hi_] +
                       rel_w[(h * DK + dd1) * DD + wi];
            split_pack2(v0, v1, ph[j], pl[j]);
        }
        size_t base = ((size_t)(b * HEADS + h) * NTOK + n) * DQK + DK;
        uint4* dh = (uint4*)(gQhi + base);
        uint4* dl = (uint4*)(gQlo + base);
#pragma unroll
        for (int q = 0; q < 4; q++) {
            dh[q] = make_uint4(ph[4*q], ph[4*q+1], ph[4*q+2], ph[4*q+3]);
            dl[q] = make_uint4(pl[4*q], pl[4*q+1], pl[4*q+2], pl[4*q+3]);
        }
    } else if (bid < 408) {
        // ---- wsplit ----
        int wb = bid - 216;
        int p = wb / 64;
        int bx = wb % 64;
        const float* w = (p == 0) ? wq : (p == 1) ? wk : wv;
        int gid = bx * 256 + tid;
        int o = gid >> 6;
        int c4 = (gid & 63) * 4;
        float4 v = *(const float4*)&w[o * CDIM + c4];
        uint32_t h01, l01, h23, l23;
        split_pack2(v.x, v.y, h01, l01);
        split_pack2(v.z, v.w, h23, l23);
        size_t base = ((size_t)p * CDIM + o) * CDIM + c4;
        *(uint2*)(gWhi + base) = make_uint2(h01, h23);
        *(uint2*)(gWlo + base) = make_uint2(l01, l23);
    } else {
        // ---- xsplit ----
        int xb = bid - 408;
        int nt = xb % 27;
        int ct = (xb / 27) % 4;
        int b = xb / 108;
        int n0 = nt * 64, c0 = ct * 64;
        const float* xb_p = x + ((size_t)b * CDIM + c0) * NTOK + n0;
        for (int u = tid; u < 64 * 16; u += 256) {
            int c = u >> 4, nv = (u & 15) * 4;
            *(float4*)&Xs[c][nv] = *(const float4*)&xb_p[(size_t)c * NTOK + nv];
        }
        __syncthreads();
        int n = tid >> 2, cq = (tid & 3) * 16;
        size_t base = ((size_t)b * NTOK + n0 + n) * CDIM + c0 + cq;
        uint32_t hw[8], lw[8];
#pragma unroll
        for (int j = 0; j < 8; j++)
            split_pack2(Xs[cq + 2*j][n], Xs[cq + 2*j + 1][n], hw[j], lw[j]);
        *(uint4*)(gXThi + base)     = make_uint4(hw[0], hw[1], hw[2], hw[3]);
        *(uint4*)(gXThi + base + 8) = make_uint4(hw[4], hw[5], hw[6], hw[7]);
        *(uint4*)(gXTlo + base)     = make_uint4(lw[0], lw[1], lw[2], lw[3]);
        *(uint4*)(gXTlo + base + 8) = make_uint4(lw[4], lw[5], lw[6], lw[7]);
    }
}

// ---------------------------------------------------------------------------
// Kernel 2: projections, 128o x 64n tiles, cp.async 2-stage. (unchanged)
// ---------------------------------------------------------------------------
#define PRS 144
#define PW_HI 0
#define PW_LO (128 * PRS)
#define PX_HI (2 * 128 * PRS)
#define PX_LO (PX_HI + 64 * PRS)
#define PBUF  (PX_LO + 64 * PRS)
#define PSM_BYTES (2 * PBUF)

__global__ __launch_bounds__(256) void proj_kernel(
    const float* __restrict__ bq, const float* __restrict__ bk,
    const float* __restrict__ bv) {
    extern __shared__ __align__(16) char psmem[];
    uint32_t sb = smem_u32(psmem);
    int tid = threadIdx.x, lane = tid & 31, w = tid >> 5;
    int nt = blockIdx.x, ot = blockIdx.y;
    int b = blockIdx.z / 3, p = blockIdx.z % 3;
    const float* bias = (p == 0) ? bq : (p == 1) ? bk : bv;
    int o0 = ot * 128, n0 = nt * 64;
    int wo = w * 16;

    const __nv_bfloat16* WhiG = gWhi + (size_t)p * CDIM * CDIM;
    const __nv_bfloat16* WloG = gWlo + (size_t)p * CDIM * CDIM;
    const __nv_bfloat16* XhiG = gXThi + (size_t)b * NTOK * CDIM;
    const __nv_bfloat16* XloG = gXTlo + (size_t)b * NTOK * CDIM;

    int a_r = lane & 15, a_c = lane >> 4;
    int b_r = lane & 7;
    int b_half = (lane >> 3) & 1;
    int b_blk = lane >> 4;

    int r1 = tid >> 3, c1 = tid & 7;
    const __nv_bfloat16 *wh1 = WhiG + (size_t)(o0 + r1) * CDIM + c1 * 8;
    const __nv_bfloat16 *wl1 = WloG + (size_t)(o0 + r1) * CDIM + c1 * 8;
    const __nv_bfloat16 *xh1 = XhiG + (size_t)(n0 + r1) * CDIM + c1 * 8;
    const __nv_bfloat16 *xl1 = XloG + (size_t)(n0 + r1) * CDIM + c1 * 8;

#define PROJ_COPY(ck, base)                                                        \
    do {                                                                           \
        uint32_t _b = (base);                                                      \
        uint32_t soff = r1 * PRS + c1 * 16;                                        \
        cp16(_b + PW_HI + soff, wh1 + (ck) * 64);                                  \
        cp16(_b + PW_LO + soff, wl1 + (ck) * 64);                                  \
        cp16(_b + PW_HI + soff + 32 * PRS, wh1 + 32 * CDIM + (ck) * 64);           \
        cp16(_b + PW_LO + soff + 32 * PRS, wl1 + 32 * CDIM + (ck) * 64);           \
        cp16(_b + PW_HI + soff + 64 * PRS, wh1 + 64 * CDIM + (ck) * 64);           \
        cp16(_b + PW_LO + soff + 64 * PRS, wl1 + 64 * CDIM + (ck) * 64);           \
        cp16(_b + PW_HI + soff + 96 * PRS, wh1 + 96 * CDIM + (ck) * 64);           \
        cp16(_b + PW_LO + soff + 96 * PRS, wl1 + 96 * CDIM + (ck) * 64);           \
        cp16(_b + PX_HI + soff, xh1 + (ck) * 64);                                  \
        cp16(_b + PX_LO + soff, xl1 + (ck) * 64);                                  \
        cp16(_b + PX_HI + soff + 32 * PRS, xh1 + 32 * CDIM + (ck) * 64);           \
        cp16(_b + PX_LO + soff + 32 * PRS, xl1 + 32 * CDIM + (ck) * 64);           \
        asm volatile("cp.async.commit_group;" ::: "memory");                       \
    } while (0)

    PROJ_COPY(0, sb);

    float S[8][4] = {};

#pragma unroll
    for (int ck = 0; ck < 4; ck++) {
        uint32_t bufb = sb + (ck & 1) * PBUF;
        asm volatile("cp.async.wait_group 0;" ::: "memory");
        __syncthreads();
        if (ck < 3) PROJ_COPY(ck + 1, sb + ((ck + 1) & 1) * PBUF);

        uint32_t abase = bufb + (wo + a_r) * PRS + a_c * 16;
#pragma unroll
        for (int kc = 0; kc < 4; kc++) {
            uint32_t Ahi[4], Alo[4];
            ldsm4(abase + PW_HI + kc * 32, Ahi);
            ldsm4(abase + PW_LO + kc * 32, Alo);
#pragma unroll
            for (int np = 0; np < 4; np++) {
                uint32_t rowb = bufb + (uint32_t)((np * 16 + b_blk * 8 + b_r) * PRS +
                                                  b_half * 16 + kc * 32);
                uint32_t bh4[4], bl4[4];
                ldsm4(rowb + PX_HI, bh4);
                ldsm4(rowb + PX_LO, bl4);
                mma16816(S[2 * np],     Ahi, bh4[0], bh4[1]);
                mma16816(S[2 * np],     Ahi, bl4[0], bl4[1]);
                mma16816(S[2 * np],     Alo, bh4[0], bh4[1]);
                mma16816(S[2 * np + 1], Ahi, bh4[2], bh4[3]);
                mma16816(S[2 * np + 1], Ahi, bl4[2], bl4[3]);
                mma16816(S[2 * np + 1], Alo, bh4[2], bh4[3]);
            }
        }
    }

    // ---- stage C-frags to fp32 smem [128][68] (overlays stage 0, dead) ----
    float* Sg = (float*)psmem;
    int g = lane >> 2, t2 = lane & 3;
#pragma unroll
    for (int np = 0; np < 4; np++)
#pragma unroll
        for (int s8 = 0; s8 < 2; s8++) {
            int ti = 2 * np + s8;
            int col = np * 16 + s8 * 8 + t2 * 2;
            Sg[(wo + g) * 68 + col]         = S[ti][0];
            Sg[(wo + g) * 68 + col + 1]     = S[ti][1];
            Sg[(wo + g + 8) * 68 + col]     = S[ti][2];
            Sg[(wo + g + 8) * 68 + col + 1] = S[ti][3];
        }
    __syncthreads();

    // ---- packed split-bf16 scatter (two 64-row halves) ----
    int tx = tid & 15, ty = tid >> 4;
#pragma unroll
    for (int half = 0; half < 2; half++) {
        int obl = half * 64 + ty * 4;
        int ob = o0 + obl;
        int h = ob >> 5, d0 = ob & 31;
        int bh = b * HEADS + h;
        float bv0 = bias[ob], bv1 = bias[ob + 1], bv2 = bias[ob + 2], bv3 = bias[ob + 3];
        float a0[4], a1[4], a2[4], a3[4];
#pragma unroll
        for (int i = 0; i < 4; i++) {
            a0[i] = Sg[(obl + 0) * 68 + tx * 4 + i] + bv0;
            a1[i] = Sg[(obl + 1) * 68 + tx * 4 + i] + bv1;
            a2[i] = Sg[(obl + 2) * 68 + tx * 4 + i] + bv2;
            a3[i] = Sg[(obl + 3) * 68 + tx * 4 + i] + bv3;
        }
        if (p == 2) {
            float* rows[4] = {a0, a1, a2, a3};
#pragma unroll
            for (int r = 0; r < 4; r++) {
                uint32_t h01, l01, h23, l23;
                split_pack2(rows[r][0], rows[r][1], h01, l01);
                split_pack2(rows[r][2], rows[r][3], h23, l23);
                size_t base = ((size_t)bh * DK + d0 + r) * NTOK + n0 + tx * 4;
                *(uint2*)(gVhi + base) = make_uint2(h01, h23);
                *(uint2*)(gVlo + base) = make_uint2(l01, l23);
            }
        } else {
#pragma unroll
            for (int i = 0; i < 4; i++) {
                int n = n0 + tx * 4 + i;
                uint32_t h01, l01, h23, l23;
                split_pack2(a0[i], a1[i], h01, l01);
                split_pack2(a2[i], a3[i], h23, l23);
                size_t rowb = ((size_t)bh * NTOK + n) * DQK;
                if (p == 0) {
                    *(uint2*)(gQhi + rowb + d0) = make_uint2(h01, h23);
                    *(uint2*)(gQlo + rowb + d0) = make_uint2(l01, l23);
                    *(uint2*)(gKhi + rowb + DK + d0) = make_uint2(h01, h23);
                    *(uint2*)(gKlo + rowb + DK + d0) = make_uint2(l01, l23);
                } else {
                    *(uint2*)(gKhi + rowb + d0) = make_uint2(h01, h23);
                    *(uint2*)(gKlo + rowb + d0) = make_uint2(l01, l23);
                }
            }
        }
    }
#undef PROJ_COPY
}

// ---------------------------------------------------------------------------
// Kernel 3: flash attention, split-K over j, double-buffered K/V,
// fused split-K combine (last CTA per (qt,bh) finishes).
// ---------------------------------------------------------------------------
#define RS 144
#define QS_HI 0
#define QS_LO (128 * RS)
#define BKH 0
#define BKL (64 * RS)
#define BVH (2 * 64 * RS)
#define BVL (BVH + 32 * RS)
#define KVBUF (BVL + 32 * RS)
#define BUF0_OFF (2 * 128 * RS)
#define BUF1_OFF 0
#define SM_BYTES (BUF0_OFF + KVBUF)

__global__ __launch_bounds__(256, 2) void attn_kernel(float* __restrict__ out) {
    extern __shared__ __align__(16) char smem[];
    __shared__ int sflag;
    uint32_t sb = smem_u32(smem);
    int tid = threadIdx.x, lane = tid & 31, w = tid >> 5;
    int qt = blockIdx.x, bh = blockIdx.y, sp = blockIdx.z;
    int m0 = qt * 128;
    int j0 = (sp == 0) ? 0 : 13;
    int j1 = (sp == 0) ? 13 : JTILES;

    const __nv_bfloat16* QhiG = gQhi + (size_t)bh * NTOK * DQK;
    const __nv_bfloat16* QloG = gQlo + (size_t)bh * NTOK * DQK;
    const __nv_bfloat16* KhiG = gKhi + (size_t)bh * NTOK * DQK;
    const __nv_bfloat16* KloG = gKlo + (size_t)bh * NTOK * DQK;
    const __nv_bfloat16* VhiG = gVhi + (size_t)bh * DK * NTOK;
    const __nv_bfloat16* VloG = gVlo + (size_t)bh * DK * NTOK;

    for (int u = tid; u < 1024; u += 256) {
        int r = u >> 3, c = u & 7;
        int gr = m0 + r; if (gr > NTOK - 1) gr = NTOK - 1;
        *(uint4*)(smem + QS_HI + r * RS + c * 16) =
            *(const uint4*)(QhiG + (size_t)gr * DQK + c * 8);
        *(uint4*)(smem + QS_LO + r * RS + c * 16) =
            *(const uint4*)(QloG + (size_t)gr * DQK + c * 8);
    }
    __syncthreads();

    int a_r = lane & 15, a_c = lane >> 4;
    int b_r = lane & 7;
    int b_half = (lane >> 3) & 1;
    int b_blk = lane >> 4;

    uint32_t Ahi[4][4], Alo[4][4];
    {
        uint32_t base = sb + (w * 16 + a_r) * RS + a_c * 16;
#pragma unroll
        for (int kc = 0; kc < 4; kc++) {
            ldsm4(base + QS_HI + kc * 32, Ahi[kc]);
            ldsm4(base + QS_LO + kc * 32, Alo[kc]);
        }
    }

    int r1 = tid >> 3, c1 = tid & 7;
    const __nv_bfloat16* kh1 = KhiG + c1 * 8;
    const __nv_bfloat16* kl1 = KloG + c1 * 8;
    const __nv_bfloat16* vh1 = VhiG + (size_t)r1 * NTOK + c1 * 8;
    const __nv_bfloat16* vl1 = VloG + (size_t)r1 * NTOK + c1 * 8;

    {
        int n0 = j0 * 64;
        uint4 k0 = *(const uint4*)(kh1 + (size_t)(n0 + r1) * DQK);
        uint4 k1 = *(const uint4*)(kl1 + (size_t)(n0 + r1) * DQK);
        uint4 k2 = *(const uint4*)(kh1 + (size_t)(n0 + r1 + 32) * DQK);
        uint4 k3 = *(const uint4*)(kl1 + (size_t)(n0 + r1 + 32) * DQK);
        uint4 v0 = *(const uint4*)(vh1 + n0);
        uint4 v1 = *(const uint4*)(vl1 + n0);
        char* bp = smem + BUF0_OFF;
        *(uint4*)(bp + BKH + r1 * RS + c1 * 16) = k0;
        *(uint4*)(bp + BKL + r1 * RS + c1 * 16) = k1;
        *(uint4*)(bp + BKH + (r1 + 32) * RS + c1 * 16) = k2;
        *(uint4*)(bp + BKL + (r1 + 32) * RS + c1 * 16) = k3;
        *(uint4*)(bp + BVH + r1 * RS + c1 * 16) = v0;
        *(uint4*)(bp + BVL + r1 * RS + c1 * 16) = v1;
    }
    __syncthreads();

    float O[4][4] = {};
    float lacc0 = 0.f, lacc1 = 0.f;

    for (int jt = j0; jt < j1; jt++) {
        int cur = (jt - j0) & 1;
        uint32_t bufb = sb + (cur ? BUF1_OFF : BUF0_OFF);
        char* nbp = smem + (cur ? BUF0_OFF : BUF1_OFF);
        bool have_next = (jt + 1 < j1);

        uint4 k0, k1, k2, k3, v0, v1;
        if (have_next) {
            int nn = (jt + 1) * 64;
            k0 = *(const uint4*)(kh1 + (size_t)(nn + r1) * DQK);
            k1 = *(const uint4*)(kl1 + (size_t)(nn + r1) * DQK);
            k2 = *(const uint4*)(kh1 + (size_t)(nn + r1 + 32) * DQK);
            k3 = *(const uint4*)(kl1 + (size_t)(nn + r1 + 32) * DQK);
            v0 = *(const uint4*)(vh1 + nn);
            v1 = *(const uint4*)(vl1 + nn);
        }

        float S[8][4] = {};
#pragma unroll
        for (int np = 0; np < 4; np++) {
            uint32_t rowb = bufb + (uint32_t)((np * 16 + b_blk * 8 + b_r) * RS + b_half * 16);
#pragma unroll
            for (int kc = 0; kc < 4; kc++) {
                uint32_t bh4[4], bl4[4];
                ldsm4(rowb + BKH + kc * 32, bh4);
                ldsm4(rowb + BKL + kc * 32, bl4);
                mma16816(S[2 * np],     Ahi[kc], bh4[0], bh4[1]);
                mma16816(S[2 * np],     Ahi[kc], bl4[0], bl4[1]);
                mma16816(S[2 * np],     Alo[kc], bh4[0], bh4[1]);
                mma16816(S[2 * np + 1], Ahi[kc], bh4[2], bh4[3]);
                mma16816(S[2 * np + 1], Ahi[kc], bl4[2], bl4[3]);
                mma16816(S[2 * np + 1], Alo[kc], bh4[2], bh4[3]);
            }
        }

        uint32_t Phi[8][2], Plo[8][2];
#pragma unroll
        for (int t = 0; t < 8; t++) {
            float p0 = __expf(S[t][0] - EXP_SHIFT);
            float p1 = __expf(S[t][1] - EXP_SHIFT);
            float p2 = __expf(S[t][2] - EXP_SHIFT);
            float p3 = __expf(S[t][3] - EXP_SHIFT);
            lacc0 += p0 + p1;
            lacc1 += p2 + p3;
            split_pack2(p0, p1, Phi[t][0], Plo[t][0]);
            split_pack2(p2, p3, Phi[t][1], Plo[t][1]);
        }

#pragma unroll
        for (int kc = 0; kc < 4; kc++) {
            int t = kc * 2;
            uint32_t Aph[4] = {Phi[t][0], Phi[t][1], Phi[t + 1][0], Phi[t + 1][1]};
            uint32_t Apl[4] = {Plo[t][0], Plo[t][1], Plo[t + 1][0], Plo[t + 1][1]};
#pragma unroll
            for (int ndp = 0; ndp < 2; ndp++) {
                uint32_t vb = bufb + (uint32_t)((ndp * 16 + b_blk * 8 + b_r) * RS +
                                                b_half * 16 + kc * 32) + BVH;
                uint32_t vh4[4], vl4[4];
                ldsm4(vb, vh4);
                ldsm4(vb + (BVL - BVH), vl4);
                mma16816(O[2 * ndp],     Aph, vh4[0], vh4[1]);
                mma16816(O[2 * ndp],     Aph, vl4[0], vl4[1]);
                mma16816(O[2 * ndp],     Apl, vh4[0], vh4[1]);
                mma16816(O[2 * ndp + 1], Aph, vh4[2], vh4[3]);
                mma16816(O[2 * ndp + 1], Aph, vl4[2], vl4[3]);
                mma16816(O[2 * ndp + 1], Apl, vh4[2], vh4[3]);
            }
        }

        if (have_next) {
            *(uint4*)(nbp + BKH + r1 * RS + c1 * 16) = k0;
            *(uint4*)(nbp + BKL + r1 * RS + c1 * 16) = k1;
            *(uint4*)(nbp + BKH + (r1 + 32) * RS + c1 * 16) = k2;
            *(uint4*)(nbp + BKL + (r1 + 32) * RS + c1 * 16) = k3;
            *(uint4*)(nbp + BVH + r1 * RS + c1 * 16) = v0;
            *(uint4*)(nbp + BVL + r1 * RS + c1 * 16) = v1;
        }
        __syncthreads();
    }

    // ---- reduce l across quad ----
    lacc0 += __shfl_xor_sync(0xffffffffu, lacc0, 1);
    lacc0 += __shfl_xor_sync(0xffffffffu, lacc0, 2);
    lacc1 += __shfl_xor_sync(0xffffffffu, lacc1, 1);
    lacc1 += __shfl_xor_sync(0xffffffffu, lacc1, 2);

    float* Op = (sp == 0) ? gOp0 : gOp1;
    float* Lp = (sp == 0) ? gLp0 : gLp1;

    int g = lane >> 2, t2 = lane & 3;
    int mr0 = m0 + w * 16 + g;
    int mr1 = mr0 + 8;
    size_t ob = (size_t)bh * DK * NTOK;

    // ---- publish my partial ----
#pragma unroll
    for (int nd = 0; nd < 4; nd++) {
        int d0 = nd * 8 + t2 * 2;
        if (mr0 < NTOK) {
            Op[ob + (size_t)d0 * NTOK + mr0]       = O[nd][0];
            Op[ob + (size_t)(d0 + 1) * NTOK + mr0] = O[nd][1];
        }
        if (mr1 < NTOK) {
            Op[ob + (size_t)d0 * NTOK + mr1]       = O[nd][2];
            Op[ob + (size_t)(d0 + 1) * NTOK + mr1] = O[nd][3];
        }
    }
    if (t2 == 0) {
        if (mr0 < NTOK) Lp[bh * NTOK + mr0] = lacc0;
        if (mr1 < NTOK) Lp[bh * NTOK + mr1] = lacc1;
    }

    // ---- last-CTA-finishes combine ----
    __threadfence();
    __syncthreads();
    if (tid == 0) sflag = atomicAdd(&gCnt[qt * BH + bh], 1);
    __syncthreads();
    if (sflag == 1) {
        const float* Oo = (sp == 0) ? gOp1 : gOp0;
        const float* Lo = (sp == 0) ? gLp1 : gLp0;
        float lo0 = (mr0 < NTOK) ? __ldcg(&Lo[bh * NTOK + mr0]) : 1.f;
        float lo1 = (mr1 < NTOK) ? __ldcg(&Lo[bh * NTOK + mr1]) : 1.f;
        float inv0 = 1.0f / (lacc0 + lo0);
        float inv1 = 1.0f / (lacc1 + lo1);
        size_t outb = ((size_t)(bh >> 3) * CDIM + (bh & 7) * DK) * NTOK;
#pragma unroll
        for (int nd = 0; nd < 4; nd++) {
            int d0 = nd * 8 + t2 * 2;
            if (mr0 < NTOK) {
                float e0 = __ldcg(&Oo[ob + (size_t)d0 * NTOK + mr0]);
                float e1 = __ldcg(&Oo[ob + (size_t)(d0 + 1) * NTOK + mr0]);
                out[outb + (size_t)d0 * NTOK + mr0]       = (O[nd][0] + e0) * inv0;
                out[outb + (size_t)(d0 + 1) * NTOK + mr0] = (O[nd][1] + e1) * inv0;
            }
            if (mr1 < NTOK) {
                float e2 = __ldcg(&Oo[ob + (size_t)d0 * NTOK + mr1]);
                float e3 = __ldcg(&Oo[ob + (size_t)(d0 + 1) * NTOK + mr1]);
                out[outb + (size_t)d0 * NTOK + mr1]       = (O[nd][2] + e2) * inv1;
                out[outb + (size_t)(d0 + 1) * NTOK + mr1] = (O[nd][3] + e3) * inv1;
            }
        }
    }
}

// ---------------------------------------------------------------------------
extern "C" void kernel_launch(void* const* d_in, const int* in_sizes, int n_in,
                              void* d_out, int out_size) {
    const float* x     = (const float*)d_in[0];
    const float* wq    = (const float*)d_in[1];
    const float* bq    = (const float*)d_in[2];
    const float* wk    = (const float*)d_in[3];
    const float* bk    = (const float*)d_in[4];
    const float* wv    = (const float*)d_in[5];
    const float* bv    = (const float*)d_in[6];
    const float* rel_d = (const float*)d_in[7];
    const float* rel_h = (const float*)d_in[8];
    const float* rel_w = (const float*)d_in[9];
    float* out = (float*)d_out;

    cudaFuncSetAttribute(attn_kernel,
                         cudaFuncAttributeMaxDynamicSharedMemorySize, SM_BYTES);
    cudaFuncSetAttribute(proj_kernel,
                         cudaFuncAttributeMaxDynamicSharedMemorySize, PSM_BYTES);

    prep_kernel<<<840, 256>>>(x, wq, wk, wv, rel_d, rel_h, rel_w);
    {
        dim3 grid(NTOK / 64, 2, BATCH * 3);
        proj_kernel<<<grid, 256, PSM_BYTES>>>(bq, bk, bv);
    }
    {
        dim3 grid(QTILES, BH, 2);
        attn_kernel<<<grid, 256, SM_BYTES>>>(out);
    }
}

// round 16
// speedup vs baseline: 1.0159x; 1.0159x over previous
#include <cuda_runtime.h>
#include <cuda_bf16.h>
#include <math.h>
#include <stdint.h>

#define HEADS 8
#define BATCH 4
#define CDIM 256
#define DK 32
#define DQK 64
#define DD 12
#define NTOK 1728
#define BH 32
#define JTILES 27
#define QTILES 14
#define EXP_SHIFT 10.0f

// ---------------- global scratch ----------------
__device__ __nv_bfloat16 gQhi[BH * NTOK * DQK];
__device__ __nv_bfloat16 gQlo[BH * NTOK * DQK];
__device__ __nv_bfloat16 gKhi[BH * NTOK * DQK];
__device__ __nv_bfloat16 gKlo[BH * NTOK * DQK];
__device__ __nv_bfloat16 gVhi[BH * DK * NTOK];
__device__ __nv_bfloat16 gVlo[BH * DK * NTOK];
__device__ __nv_bfloat16 gWhi[3 * CDIM * CDIM];
__device__ __nv_bfloat16 gWlo[3 * CDIM * CDIM];
__device__ __nv_bfloat16 gXThi[BATCH * NTOK * CDIM];
__device__ __nv_bfloat16 gXTlo[BATCH * NTOK * CDIM];
// split-K attention partials (additive thanks to no-max shifted softmax)
__device__ float gOp0[BH * DK * NTOK];
__device__ float gOp1[BH * DK * NTOK];
__device__ float gLp0[BH * NTOK];
__device__ float gLp1[BH * NTOK];

// ---------------- helpers ----------------
__device__ __forceinline__ uint32_t smem_u32(const void* p) {
    uint32_t a;
    asm("{ .reg .u64 t; cvta.to.shared.u64 t, %1; cvt.u32.u64 %0, t; }"
        : "=r"(a) : "l"(p));
    return a;
}
__device__ __forceinline__ void ldsm4(uint32_t addr, uint32_t r[4]) {
    asm volatile("ldmatrix.sync.aligned.m8n8.x4.shared.b16 {%0,%1,%2,%3}, [%4];"
        : "=r"(r[0]), "=r"(r[1]), "=r"(r[2]), "=r"(r[3]) : "r"(addr));
}
__device__ __forceinline__ void mma16816(float c[4], const uint32_t a[4],
                                         uint32_t b0, uint32_t b1) {
    asm volatile(
        "mma.sync.aligned.m16n8k16.row.col.f32.bf16.bf16.f32 "
        "{%0,%1,%2,%3}, {%4,%5,%6,%7}, {%8,%9}, {%0,%1,%2,%3};"
        : "+f"(c[0]), "+f"(c[1]), "+f"(c[2]), "+f"(c[3])
        : "r"(a[0]), "r"(a[1]), "r"(a[2]), "r"(a[3]), "r"(b0), "r"(b1));
}
__device__ __forceinline__ uint32_t cvt_bf16x2(float lo, float hi) {
    uint32_t d;
    asm("cvt.rn.bf16x2.f32 %0, %1, %2;" : "=r"(d) : "f"(hi), "f"(lo));
    return d;
}
__device__ __forceinline__ float bflo_f(uint32_t p) { return __uint_as_float(p << 16); }
__device__ __forceinline__ float bfhi_f(uint32_t p) { return __uint_as_float(p & 0xffff0000u); }
__device__ __forceinline__ void split_pack2(float v0, float v1,
                                            uint32_t& hi, uint32_t& lo) {
    hi = cvt_bf16x2(v0, v1);
    lo = cvt_bf16x2(v0 - bflo_f(hi), v1 - bfhi_f(hi));
}
__device__ __forceinline__ void cp16(uint32_t dst, const void* src) {
    asm volatile("cp.async.cg.shared.global [%0], [%1], 16;"
                 :: "r"(dst), "l"(src) : "memory");
}

// ---------------------------------------------------------------------------
// Kernel 1 (merged prep): pos | wsplit | xsplit.
//   blocks [0,224)    : pos, block = (bh, nchunk of 256); rel cached in smem
//   blocks [224,416)  : wsplit (192 blocks)
//   blocks [416,848)  : xsplit (432 blocks)
// ---------------------------------------------------------------------------
__global__ __launch_bounds__(256) void prep_kernel(
    const float* __restrict__ x,
    const float* __restrict__ wq, const float* __restrict__ wk,
    const float* __restrict__ wv,
    const float* __restrict__ rel_d, const float* __restrict__ rel_h,
    const float* __restrict__ rel_w) {
    __shared__ float Xs[64][68];     // also reused as rel cache by pos branch
    int bid = blockIdx.x;
    int tid = threadIdx.x;

    if (bid < 224) {
        // ---- pos: bh = bid/7, n = (bid%7)*256 + tid ----
        int bh = bid / 7;
        int nc = bid % 7;
        int b = bh >> 3, h = bh & 7;
        float* sRd = (float*)Xs;         // [32*12]
        float* sRh = sRd + 384;
        float* sRw = sRh + 384;
        for (int u = tid; u < 384; u += 256) {
            sRd[u] = rel_d[h * 384 + u];
            sRh[u] = rel_h[h * 384 + u];
            sRw[u] = rel_w[h * 384 + u];
        }
        __syncthreads();
        int n = nc * 256 + tid;
        if (n < NTOK) {
            int hi_ = n % DD;
            int wi = (n / DD) % DD;
            int di = n / (DD * DD);
            uint32_t ph[16], pl[16];
#pragma unroll
            for (int j = 0; j < 16; j++) {
                int dd0 = 2 * j, dd1 = 2 * j + 1;
                float v0 = sRd[dd0 * DD + di] + sRh[dd0 * DD + hi_] + sRw[dd0 * DD + wi];
                float v1 = sRd[dd1 * DD + di] + sRh[dd1 * DD + hi_] + sRw[dd1 * DD + wi];
                split_pack2(v0, v1, ph[j], pl[j]);
            }
            size_t base = ((size_t)(b * HEADS + h) * NTOK + n) * DQK + DK;
            uint4* dh = (uint4*)(gQhi + base);
            uint4* dl = (uint4*)(gQlo + base);
#pragma unroll
            for (int q = 0; q < 4; q++) {
                dh[q] = make_uint4(ph[4*q], ph[4*q+1], ph[4*q+2], ph[4*q+3]);
                dl[q] = make_uint4(pl[4*q], pl[4*q+1], pl[4*q+2], pl[4*q+3]);
            }
        }
    } else if (bid < 416) {
        // ---- wsplit ----
        int wb = bid - 224;
        int p = wb / 64;
        int bx = wb % 64;
        const float* w = (p == 0) ? wq : (p == 1) ? wk : wv;
        int gid = bx * 256 + tid;
        int o = gid >> 6;
        int c4 = (gid & 63) * 4;
        float4 v = *(const float4*)&w[o * CDIM + c4];
        uint32_t h01, l01, h23, l23;
        split_pack2(v.x, v.y, h01, l01);
        split_pack2(v.z, v.w, h23, l23);
        size_t base = ((size_t)p * CDIM + o) * CDIM + c4;
        *(uint2*)(gWhi + base) = make_uint2(h01, h23);
        *(uint2*)(gWlo + base) = make_uint2(l01, l23);
    } else {
        // ---- xsplit ----
        int xb = bid - 416;
        int nt = xb % 27;
        int ct = (xb / 27) % 4;
        int b = xb / 108;
        int n0 = nt * 64, c0 = ct * 64;
        const float* xb_p = x + ((size_t)b * CDIM + c0) * NTOK + n0;
        for (int u = tid; u < 64 * 16; u += 256) {
            int c = u >> 4, nv = (u & 15) * 4;
            *(float4*)&Xs[c][nv] = *(const float4*)&xb_p[(size_t)c * NTOK + nv];
        }
        __syncthreads();
        int n = tid >> 2, cq = (tid & 3) * 16;
        size_t base = ((size_t)b * NTOK + n0 + n) * CDIM + c0 + cq;
        uint32_t hw[8], lw[8];
#pragma unroll
        for (int j = 0; j < 8; j++)
            split_pack2(Xs[cq + 2*j][n], Xs[cq + 2*j + 1][n], hw[j], lw[j]);
        *(uint4*)(gXThi + base)     = make_uint4(hw[0], hw[1], hw[2], hw[3]);
        *(uint4*)(gXThi + base + 8) = make_uint4(hw[4], hw[5], hw[6], hw[7]);
        *(uint4*)(gXTlo + base)     = make_uint4(lw[0], lw[1], lw[2], lw[3]);
        *(uint4*)(gXTlo + base + 8) = make_uint4(lw[4], lw[5], lw[6], lw[7]);
    }
}

// ---------------------------------------------------------------------------
// Kernel 2: projections, 128o x 64n tiles, cp.async 2-stage. (unchanged)
// ---------------------------------------------------------------------------
#define PRS 144
#define PW_HI 0
#define PW_LO (128 * PRS)
#define PX_HI (2 * 128 * PRS)
#define PX_LO (PX_HI + 64 * PRS)
#define PBUF  (PX_LO + 64 * PRS)
#define PSM_BYTES (2 * PBUF)

__global__ __launch_bounds__(256) void proj_kernel(
    const float* __restrict__ bq, const float* __restrict__ bk,
    const float* __restrict__ bv) {
    extern __shared__ __align__(16) char psmem[];
    uint32_t sb = smem_u32(psmem);
    int tid = threadIdx.x, lane = tid & 31, w = tid >> 5;
    int nt = blockIdx.x, ot = blockIdx.y;
    int b = blockIdx.z / 3, p = blockIdx.z % 3;
    const float* bias = (p == 0) ? bq : (p == 1) ? bk : bv;
    int o0 = ot * 128, n0 = nt * 64;
    int wo = w * 16;

    const __nv_bfloat16* WhiG = gWhi + (size_t)p * CDIM * CDIM;
    const __nv_bfloat16* WloG = gWlo + (size_t)p * CDIM * CDIM;
    const __nv_bfloat16* XhiG = gXThi + (size_t)b * NTOK * CDIM;
    const __nv_bfloat16* XloG = gXTlo + (size_t)b * NTOK * CDIM;

    int a_r = lane & 15, a_c = lane >> 4;
    int b_r = lane & 7;
    int b_half = (lane >> 3) & 1;
    int b_blk = lane >> 4;

    int r1 = tid >> 3, c1 = tid & 7;
    const __nv_bfloat16 *wh1 = WhiG + (size_t)(o0 + r1) * CDIM + c1 * 8;
    const __nv_bfloat16 *wl1 = WloG + (size_t)(o0 + r1) * CDIM + c1 * 8;
    const __nv_bfloat16 *xh1 = XhiG + (size_t)(n0 + r1) * CDIM + c1 * 8;
    const __nv_bfloat16 *xl1 = XloG + (size_t)(n0 + r1) * CDIM + c1 * 8;

#define PROJ_COPY(ck, base)                                                        \
    do {                                                                           \
        uint32_t _b = (base);                                                      \
        uint32_t soff = r1 * PRS + c1 * 16;                                        \
        cp16(_b + PW_HI + soff, wh1 + (ck) * 64);                                  \
        cp16(_b + PW_LO + soff, wl1 + (ck) * 64);                                  \
        cp16(_b + PW_HI + soff + 32 * PRS, wh1 + 32 * CDIM + (ck) * 64);           \
        cp16(_b + PW_LO + soff + 32 * PRS, wl1 + 32 * CDIM + (ck) * 64);           \
        cp16(_b + PW_HI + soff + 64 * PRS, wh1 + 64 * CDIM + (ck) * 64);           \
        cp16(_b + PW_LO + soff + 64 * PRS, wl1 + 64 * CDIM + (ck) * 64);           \
        cp16(_b + PW_HI + soff + 96 * PRS, wh1 + 96 * CDIM + (ck) * 64);           \
        cp16(_b + PW_LO + soff + 96 * PRS, wl1 + 96 * CDIM + (ck) * 64);           \
        cp16(_b + PX_HI + soff, xh1 + (ck) * 64);                                  \
        cp16(_b + PX_LO + soff, xl1 + (ck) * 64);                                  \
        cp16(_b + PX_HI + soff + 32 * PRS, xh1 + 32 * CDIM + (ck) * 64);           \
        cp16(_b + PX_LO + soff + 32 * PRS, xl1 + 32 * CDIM + (ck) * 64);           \
        asm volatile("cp.async.commit_group;" ::: "memory");                       \
    } while (0)

    PROJ_COPY(0, sb);

    float S[8][4] = {};

#pragma unroll
    for (int ck = 0; ck < 4; ck++) {
        uint32_t bufb = sb + (ck & 1) * PBUF;
        asm volatile("cp.async.wait_group 0;" ::: "memory");
        __syncthreads();
        if (ck < 3) PROJ_COPY(ck + 1, sb + ((ck + 1) & 1) * PBUF);

        uint32_t abase = bufb + (wo + a_r) * PRS + a_c * 16;
#pragma unroll
        for (int kc = 0; kc < 4; kc++) {
            uint32_t Ahi[4], Alo[4];
            ldsm4(abase + PW_HI + kc * 32, Ahi);
            ldsm4(abase + PW_LO + kc * 32, Alo);
#pragma unroll
            for (int np = 0; np < 4; np++) {
                uint32_t rowb = bufb + (uint32_t)((np * 16 + b_blk * 8 + b_r) * PRS +
                                                  b_half * 16 + kc * 32);
                uint32_t bh4[4], bl4[4];
                ldsm4(rowb + PX_HI, bh4);
                ldsm4(rowb + PX_LO, bl4);
                mma16816(S[2 * np],     Ahi, bh4[0], bh4[1]);
                mma16816(S[2 * np],     Ahi, bl4[0], bl4[1]);
                mma16816(S[2 * np],     Alo, bh4[0], bh4[1]);
                mma16816(S[2 * np + 1], Ahi, bh4[2], bh4[3]);
                mma16816(S[2 * np + 1], Ahi, bl4[2], bl4[3]);
                mma16816(S[2 * np + 1], Alo, bh4[2], bh4[3]);
            }
        }
    }

    // ---- stage C-frags to fp32 smem [128][68] (overlays stage 0, dead) ----
    float* Sg = (float*)psmem;
    int g = lane >> 2, t2 = lane & 3;
#pragma unroll
    for (int np = 0; np < 4; np++)
#pragma unroll
        for (int s8 = 0; s8 < 2; s8++) {
            int ti = 2 * np + s8;
            int col = np * 16 + s8 * 8 + t2 * 2;
            Sg[(wo + g) * 68 + col]         = S[ti][0];
            Sg[(wo + g) * 68 + col + 1]     = S[ti][1];
            Sg[(wo + g + 8) * 68 + col]     = S[ti][2];
            Sg[(wo + g + 8) * 68 + col + 1] = S[ti][3];
        }
    __syncthreads();

    // ---- packed split-bf16 scatter (two 64-row halves) ----
    int tx = tid & 15, ty = tid >> 4;
#pragma unroll
    for (int half = 0; half < 2; half++) {
        int obl = half * 64 + ty * 4;
        int ob = o0 + obl;
        int h = ob >> 5, d0 = ob & 31;
        int bh = b * HEADS + h;
        float bv0 = bias[ob], bv1 = bias[ob + 1], bv2 = bias[ob + 2], bv3 = bias[ob + 3];
        float a0[4], a1[4], a2[4], a3[4];
#pragma unroll
        for (int i = 0; i < 4; i++) {
            a0[i] = Sg[(obl + 0) * 68 + tx * 4 + i] + bv0;
            a1[i] = Sg[(obl + 1) * 68 + tx * 4 + i] + bv1;
            a2[i] = Sg[(obl + 2) * 68 + tx * 4 + i] + bv2;
            a3[i] = Sg[(obl + 3) * 68 + tx * 4 + i] + bv3;
        }
        if (p == 2) {
            float* rows[4] = {a0, a1, a2, a3};
#pragma unroll
            for (int r = 0; r < 4; r++) {
                uint32_t h01, l01, h23, l23;
                split_pack2(rows[r][0], rows[r][1], h01, l01);
                split_pack2(rows[r][2], rows[r][3], h23, l23);
                size_t base = ((size_t)bh * DK + d0 + r) * NTOK + n0 + tx * 4;
                *(uint2*)(gVhi + base) = make_uint2(h01, h23);
                *(uint2*)(gVlo + base) = make_uint2(l01, l23);
            }
        } else {
#pragma unroll
            for (int i = 0; i < 4; i++) {
                int n = n0 + tx * 4 + i;
                uint32_t h01, l01, h23, l23;
                split_pack2(a0[i], a1[i], h01, l01);
                split_pack2(a2[i], a3[i], h23, l23);
                size_t rowb = ((size_t)bh * NTOK + n) * DQK;
                if (p == 0) {
                    *(uint2*)(gQhi + rowb + d0) = make_uint2(h01, h23);
                    *(uint2*)(gQlo + rowb + d0) = make_uint2(l01, l23);
                    *(uint2*)(gKhi + rowb + DK + d0) = make_uint2(h01, h23);
                    *(uint2*)(gKlo + rowb + DK + d0) = make_uint2(l01, l23);
                } else {
                    *(uint2*)(gKhi + rowb + d0) = make_uint2(h01, h23);
                    *(uint2*)(gKlo + rowb + d0) = make_uint2(l01, l23);
                }
            }
        }
    }
#undef PROJ_COPY
}

// ---------------------------------------------------------------------------
// Kernel 3: flash attention, split-K over j, double-buffered K/V (R14 exact).
// ---------------------------------------------------------------------------
#define RS 144
#define QS_HI 0
#define QS_LO (128 * RS)
#define BKH 0
#define BKL (64 * RS)
#define BVH (2 * 64 * RS)
#define BVL (BVH + 32 * RS)
#define KVBUF (BVL + 32 * RS)
#define BUF0_OFF (2 * 128 * RS)
#define BUF1_OFF 0
#define SM_BYTES (BUF0_OFF + KVBUF)

__global__ __launch_bounds__(256, 2) void attn_kernel() {
    extern __shared__ __align__(16) char smem[];
    uint32_t sb = smem_u32(smem);
    int tid = threadIdx.x, lane = tid & 31, w = tid >> 5;
    int qt = blockIdx.x, bh = blockIdx.y, sp = blockIdx.z;
    int m0 = qt * 128;
    int j0 = (sp == 0) ? 0 : 13;
    int j1 = (sp == 0) ? 13 : JTILES;

    const __nv_bfloat16* QhiG = gQhi + (size_t)bh * NTOK * DQK;
    const __nv_bfloat16* QloG = gQlo + (size_t)bh * NTOK * DQK;
    const __nv_bfloat16* KhiG = gKhi + (size_t)bh * NTOK * DQK;
    const __nv_bfloat16* KloG = gKlo + (size_t)bh * NTOK * DQK;
    const __nv_bfloat16* VhiG = gVhi + (size_t)bh * DK * NTOK;
    const __nv_bfloat16* VloG = gVlo + (size_t)bh * DK * NTOK;

    for (int u = tid; u < 1024; u += 256) {
        int r = u >> 3, c = u & 7;
        int gr = m0 + r; if (gr > NTOK - 1) gr = NTOK - 1;
        *(uint4*)(smem + QS_HI + r * RS + c * 16) =
            *(const uint4*)(QhiG + (size_t)gr * DQK + c * 8);
        *(uint4*)(smem + QS_LO + r * RS + c * 16) =
            *(const uint4*)(QloG + (size_t)gr * DQK + c * 8);
    }
    __syncthreads();

    int a_r = lane & 15, a_c = lane >> 4;
    int b_r = lane & 7;
    int b_half = (lane >> 3) & 1;
    int b_blk = lane >> 4;

    uint32_t Ahi[4][4], Alo[4][4];
    {
        uint32_t base = sb + (w * 16 + a_r) * RS + a_c * 16;
#pragma unroll
        for (int kc = 0; kc < 4; kc++) {
            ldsm4(base + QS_HI + kc * 32, Ahi[kc]);
            ldsm4(base + QS_LO + kc * 32, Alo[kc]);
        }
    }

    int r1 = tid >> 3, c1 = tid & 7;
    const __nv_bfloat16* kh1 = KhiG + c1 * 8;
    const __nv_bfloat16* kl1 = KloG + c1 * 8;
    const __nv_bfloat16* vh1 = VhiG + (size_t)r1 * NTOK + c1 * 8;
    const __nv_bfloat16* vl1 = VloG + (size_t)r1 * NTOK + c1 * 8;

    {
        int n0 = j0 * 64;
        uint4 k0 = *(const uint4*)(kh1 + (size_t)(n0 + r1) * DQK);
        uint4 k1 = *(const uint4*)(kl1 + (size_t)(n0 + r1) * DQK);
        uint4 k2 = *(const uint4*)(kh1 + (size_t)(n0 + r1 + 32) * DQK);
        uint4 k3 = *(const uint4*)(kl1 + (size_t)(n0 + r1 + 32) * DQK);
        uint4 v0 = *(const uint4*)(vh1 + n0);
        uint4 v1 = *(const uint4*)(vl1 + n0);
        char* bp = smem + BUF0_OFF;
        *(uint4*)(bp + BKH + r1 * RS + c1 * 16) = k0;
        *(uint4*)(bp + BKL + r1 * RS + c1 * 16) = k1;
        *(uint4*)(bp + BKH + (r1 + 32) * RS + c1 * 16) = k2;
        *(uint4*)(bp + BKL + (r1 + 32) * RS + c1 * 16) = k3;
        *(uint4*)(bp + BVH + r1 * RS + c1 * 16) = v0;
        *(uint4*)(bp + BVL + r1 * RS + c1 * 16) = v1;
    }
    __syncthreads();

    float O[4][4] = {};
    float lacc0 = 0.f, lacc1 = 0.f;

    for (int jt = j0; jt < j1; jt++) {
        int cur = (jt - j0) & 1;
        uint32_t bufb = sb + (cur ? BUF1_OFF : BUF0_OFF);
        char* nbp = smem + (cur ? BUF0_OFF : BUF1_OFF);
        bool have_next = (jt + 1 < j1);

        uint4 k0, k1, k2, k3, v0, v1;
        if (have_next) {
            int nn = (jt + 1) * 64;
            k0 = *(const uint4*)(kh1 + (size_t)(nn + r1) * DQK);
            k1 = *(const uint4*)(kl1 + (size_t)(nn + r1) * DQK);
            k2 = *(const uint4*)(kh1 + (size_t)(nn + r1 + 32) * DQK);
            k3 = *(const uint4*)(kl1 + (size_t)(nn + r1 + 32) * DQK);
            v0 = *(const uint4*)(vh1 + nn);
            v1 = *(const uint4*)(vl1 + nn);
        }

        float S[8][4] = {};
#pragma unroll
        for (int np = 0; np < 4; np++) {
            uint32_t rowb = bufb + (uint32_t)((np * 16 + b_blk * 8 + b_r) * RS + b_half * 16);
#pragma unroll
            for (int kc = 0; kc < 4; kc++) {
                uint32_t bh4[4], bl4[4];
                ldsm4(rowb + BKH + kc * 32, bh4);
                ldsm4(rowb + BKL + kc * 32, bl4);
                mma16816(S[2 * np],     Ahi[kc], bh4[0], bh4[1]);
                mma16816(S[2 * np],     Ahi[kc], bl4[0], bl4[1]);
                mma16816(S[2 * np],     Alo[kc], bh4[0], bh4[1]);
                mma16816(S[2 * np + 1], Ahi[kc], bh4[2], bh4[3]);
                mma16816(S[2 * np + 1], Ahi[kc], bl4[2], bl4[3]);
                mma16816(S[2 * np + 1], Alo[kc], bh4[2], bh4[3]);
            }
        }

        uint32_t Phi[8][2], Plo[8][2];
#pragma unroll
        for (int t = 0; t < 8; t++) {
            float p0 = __expf(S[t][0] - EXP_SHIFT);
            float p1 = __expf(S[t][1] - EXP_SHIFT);
            float p2 = __expf(S[t][2] - EXP_SHIFT);
            float p3 = __expf(S[t][3] - EXP_SHIFT);
            lacc0 += p0 + p1;
            lacc1 += p2 + p3;
            split_pack2(p0, p1, Phi[t][0], Plo[t][0]);
            split_pack2(p2, p3, Phi[t][1], Plo[t][1]);
        }

#pragma unroll
        for (int kc = 0; kc < 4; kc++) {
            int t = kc * 2;
            uint32_t Aph[4] = {Phi[t][0], Phi[t][1], Phi[t + 1][0], Phi[t + 1][1]};
            uint32_t Apl[4] = {Plo[t][0], Plo[t][1], Plo[t + 1][0], Plo[t + 1][1]};
#pragma unroll
            for (int ndp = 0; ndp < 2; ndp++) {
                uint32_t vb = bufb + (uint32_t)((ndp * 16 + b_blk * 8 + b_r) * RS +
                                                b_half * 16 + kc * 32) + BVH;
                uint32_t vh4[4], vl4[4];
                ldsm4(vb, vh4);
                ldsm4(vb + (BVL - BVH), vl4);
                mma16816(O[2 * ndp],     Aph, vh4[0], vh4[1]);
                mma16816(O[2 * ndp],     Aph, vl4[0], vl4[1]);
                mma16816(O[2 * ndp],     Apl, vh4[0], vh4[1]);
                mma16816(O[2 * ndp + 1], Aph, vh4[2], vh4[3]);
                mma16816(O[2 * ndp + 1], Aph, vl4[2], vl4[3]);
                mma16816(O[2 * ndp + 1], Apl, vh4[2], vh4[3]);
            }
        }

        if (have_next) {
            *(uint4*)(nbp + BKH + r1 * RS + c1 * 16) = k0;
            *(uint4*)(nbp + BKL + r1 * RS + c1 * 16) = k1;
            *(uint4*)(nbp + BKH + (r1 + 32) * RS + c1 * 16) = k2;
            *(uint4*)(nbp + BKL + (r1 + 32) * RS + c1 * 16) = k3;
            *(uint4*)(nbp + BVH + r1 * RS + c1 * 16) = v0;
            *(uint4*)(nbp + BVL + r1 * RS + c1 * 16) = v1;
        }
        __syncthreads();
    }

    lacc0 += __shfl_xor_sync(0xffffffffu, lacc0, 1);
    lacc0 += __shfl_xor_sync(0xffffffffu, lacc0, 2);
    lacc1 += __shfl_xor_sync(0xffffffffu, lacc1, 1);
    lacc1 += __shfl_xor_sync(0xffffffffu, lacc1, 2);

    float* Op = (sp == 0) ? gOp0 : gOp1;
    float* Lp = (sp == 0) ? gLp0 : gLp1;

    int g = lane >> 2, t2 = lane & 3;
    int mr0 = m0 + w * 16 + g;
    int mr1 = mr0 + 8;
    size_t ob = (size_t)bh * DK * NTOK;
#pragma unroll
    for (int nd = 0; nd < 4; nd++) {
        int d0 = nd * 8 + t2 * 2;
        if (mr0 < NTOK) {
            Op[ob + (size_t)d0 * NTOK + mr0]       = O[nd][0];
            Op[ob + (size_t)(d0 + 1) * NTOK + mr0] = O[nd][1];
        }
        if (mr1 < NTOK) {
            Op[ob + (size_t)d0 * NTOK + mr1]       = O[nd][2];
            Op[ob + (size_t)(d0 + 1) * NTOK + mr1] = O[nd][3];
        }
    }
    if (t2 == 0) {
        if (mr0 < NTOK) Lp[bh * NTOK + mr0] = lacc0;
        if (mr1 < NTOK) Lp[bh * NTOK + mr1] = lacc1;
    }
}

// ---------------------------------------------------------------------------
// Kernel 4: combine split-K partials.
// ---------------------------------------------------------------------------
__global__ void combine_kernel(float* __restrict__ out) {
    int idx = (blockIdx.x * 256 + threadIdx.x) * 4;
    if (idx >= BH * DK * NTOK) return;
    int m = idx % NTOK;
    int bh = idx / (DK * NTOK);
    float4 o1 = *(const float4*)&gOp0[idx];
    float4 o2 = *(const float4*)&gOp1[idx];
    float4 l1 = *(const float4*)&gLp0[bh * NTOK + m];
    float4 l2 = *(const float4*)&gLp1[bh * NTOK + m];
    float4 r;
    r.x = (o1.x + o2.x) / (l1.x + l2.x);
    r.y = (o1.y + o2.y) / (l1.y + l2.y);
    r.z = (o1.z + o2.z) / (l1.z + l2.z);
    r.w = (o1.w + o2.w) / (l1.w + l2.w);
    *(float4*)&out[idx] = r;
}

// ---------------------------------------------------------------------------
extern "C" void kernel_launch(void* const* d_in, const int* in_sizes, int n_in,
                              void* d_out, int out_size) {
    const float* x     = (const float*)d_in[0];
    const float* wq    = (const float*)d_in[1];
    const float* bq    = (const float*)d_in[2];
    const float* wk    = (const float*)d_in[3];
    const float* bk    = (const float*)d_in[4];
    const float* wv    = (const float*)d_in[5];
    const float* bv    = (const float*)d_in[6];
    const float* rel_d = (const float*)d_in[7];
    const float* rel_h = (const float*)d_in[8];
    const float* rel_w = (const float*)d_in[9];
    float* out = (float*)d_out;

    cudaFuncSetAttribute(attn_kernel,
                         cudaFuncAttributeMaxDynamicSharedMemorySize, SM_BYTES);
    cudaFuncSetAttribute(proj_kernel,
                         cudaFuncAttributeMaxDynamicSharedMemorySize, PSM_BYTES);

    prep_kernel<<<848, 256>>>(x, wq, wk, wv, rel_d, rel_h, rel_w);
    {
        dim3 grid(NTOK / 64, 2, BATCH * 3);
        proj_kernel<<<grid, 256, PSM_BYTES>>>(bq, bk, bv);
    }
    {
        dim3 grid(QTILES, BH, 2);
        attn_kernel<<<grid, 256, SM_BYTES>>>();
    }
    {
        int total = BH * DK * NTOK / 4;
        combine_kernel<<<(total + 255) / 256, 256>>>(out);
    }
}